// round 14
// baseline (speedup 1.0000x reference)
#include <cuda_runtime.h>
#include <cuda_bf16.h>

#define NVERT 6890
#define NJ 24
#define NB 10
#define NP 207
#define NP8 26
#define NPP (NP8*8)
#define MAXB 1024
#define TB 8             // batches per kC block tile
#define TBH 4            // batch-pairs per thread
#define CBLK 128
#define VSPL 8
#define VCH 862
#define DB 16            // batches per kD block

typedef unsigned long long u64;

__device__ __forceinline__ u64 pack2(float x) {
    u64 r; asm("mov.b64 %0,{%1,%1};" : "=l"(r) : "f"(x)); return r;
}
__device__ __forceinline__ void unpack2(u64 v, float& a, float& b) {
    asm("mov.b64 {%0,%1},%2;" : "=f"(a), "=f"(b) : "l"(v));
}
__device__ __forceinline__ u64 fma2(u64 a, u64 b, u64 c) {
    u64 d; asm("fma.rn.f32x2 %0,%1,%2,%3;" : "=l"(d) : "l"(a), "l"(b), "l"(c)); return d;
}
__device__ __forceinline__ u64 add2(u64 a, u64 b) {
    u64 d; asm("add.rn.f32x2 %0,%1,%2;" : "=l"(d) : "l"(a), "l"(b)); return d;
}
__device__ __forceinline__ u64 splat_lo(unsigned u) {
    unsigned f = u << 16;
    u64 r; asm("mov.b64 %0,{%1,%1};" : "=l"(r) : "r"(f)); return r;
}
__device__ __forceinline__ u64 splat_hi(unsigned u) {
    unsigned f = u & 0xffff0000u;
    u64 r; asm("mov.b64 %0,{%1,%1};" : "=l"(r) : "r"(f)); return r;
}

__constant__ int c_par[NJ] = {-1, 0, 0, 0, 1, 2, 3, 4, 5, 6, 7, 8, 9, 9, 9,
                              12, 13, 14, 16, 17, 18, 19, 20, 21};

__device__ float g_JrT[NJ * 3];
__device__ float g_JrS[NJ * 3 * NB];
__device__ float g_G[MAXB * NJ * 12];
__device__ float g_lrot[MAXB * NP];

__device__ uint4 g_pdh4[(size_t)3 * NP8 * NVERT];
__device__ float g_sdT[3 * NB * NVERT];
__device__ float g_wT[NJ * NVERT];
__device__ float g_vtT[3 * NVERT];

// ---------------------------------------------------------------------------
// kTpd: pd[v][c][p] -> g_pdh4 bf16-packed, coalesced uint4 stores.
// ---------------------------------------------------------------------------
__global__ __launch_bounds__(256) void kTpd(const float* __restrict__ pd) {
    __shared__ float tile[32][33];
    int c = blockIdx.z;
    int p0 = blockIdx.x * 32, v0 = blockIdx.y * 32;
    for (int r = threadIdx.y; r < 32; r += 8) {
        int v = v0 + r, p = p0 + threadIdx.x;
        tile[r][threadIdx.x] =
            (v < NVERT && p < NP) ? pd[((size_t)v * 3 + c) * NP + p] : 0.f;
    }
    __syncthreads();
    int p8l = threadIdx.y;
    int vl = threadIdx.x;
    if (p8l < 4) {
        int p8g = (p0 >> 3) + p8l;
        int v = v0 + vl;
        if (p8g < NP8 && v < NVERT) {
            unsigned w[4];
#pragma unroll
            for (int k = 0; k < 4; ++k) {
                float f0 = tile[vl][p8l * 8 + 2 * k + 0];
                float f1 = tile[vl][p8l * 8 + 2 * k + 1];
                unsigned lo = __bfloat16_as_ushort(__float2bfloat16(f0));
                unsigned hi = __bfloat16_as_ushort(__float2bfloat16(f1));
                w[k] = lo | (hi << 16);
            }
            g_pdh4[((size_t)c * NP8 + p8g) * NVERT + v] =
                make_uint4(w[0], w[1], w[2], w[3]);
        }
    }
}

// ---------------------------------------------------------------------------
// kT3: three small transposes (z: 0=weights,1=shapedirs,2=vt)
// ---------------------------------------------------------------------------
__global__ __launch_bounds__(256) void kT3(const float* __restrict__ wgt,
                                           const float* __restrict__ sd,
                                           const float* __restrict__ vt) {
    __shared__ float tile[32][33];
    const float* in; float* out; int K;
    if (blockIdx.z == 0)      { in = wgt; out = g_wT;  K = NJ; }
    else if (blockIdx.z == 1) { in = sd;  out = g_sdT; K = 3 * NB; }
    else                      { in = vt;  out = g_vtT; K = 3; }
    int v0 = blockIdx.x * 32;
    for (int r = threadIdx.y; r < 32; r += 8) {
        int v = v0 + r, k = threadIdx.x;
        tile[r][k] = (v < NVERT && k < K) ? in[(size_t)v * K + k] : 0.f;
    }
    __syncthreads();
    for (int r = threadIdx.y; r < 32; r += 8) {
        int k = r, v = v0 + threadIdx.x;
        if (k < K && v < NVERT) out[(size_t)k * NVERT + v] = tile[threadIdx.x][r];
    }
}

// ---------------------------------------------------------------------------
// Kernel A: fold J_regressor into v_template and shapedirs.
// ---------------------------------------------------------------------------
__global__ __launch_bounds__(256) void kA(const float* __restrict__ Jr) {
    int j = blockIdx.x;
    float acc[33];
#pragma unroll
    for (int k = 0; k < 33; ++k) acc[k] = 0.f;

    for (int v = threadIdx.x; v < NVERT; v += blockDim.x) {
        float w = Jr[j * NVERT + v];
#pragma unroll
        for (int c = 0; c < 3; ++c)
            acc[c] = fmaf(w, __ldg(&g_vtT[c * NVERT + v]), acc[c]);
#pragma unroll
        for (int k = 0; k < 3 * NB; ++k)
            acc[3 + k] = fmaf(w, __ldg(&g_sdT[(size_t)k * NVERT + v]), acc[3 + k]);
    }
#pragma unroll
    for (int k = 0; k < 33; ++k) {
#pragma unroll
        for (int off = 16; off > 0; off >>= 1)
            acc[k] += __shfl_xor_sync(0xffffffffu, acc[k], off);
    }
    __shared__ float sm[33];
    if (threadIdx.x < 33) sm[threadIdx.x] = 0.f;
    __syncthreads();
    if ((threadIdx.x & 31) == 0) {
#pragma unroll
        for (int k = 0; k < 33; ++k) atomicAdd(&sm[k], acc[k]);
    }
    __syncthreads();
    if (threadIdx.x < 3) g_JrT[j * 3 + threadIdx.x] = sm[threadIdx.x];
    if (threadIdx.x >= 3 && threadIdx.x < 33)
        g_JrS[j * 3 * NB + threadIdx.x - 3] = sm[threadIdx.x];
}

// ---------------------------------------------------------------------------
// Kernel B: joints, Rodrigues, chain, G, lrot, zero joints.
// ---------------------------------------------------------------------------
__global__ __launch_bounds__(32) void kB(const float* __restrict__ betas,
                                         const float* __restrict__ thetas,
                                         const float* __restrict__ scale,
                                         float* __restrict__ joints) {
    int b = blockIdx.x;
    int t = threadIdx.x;
    __shared__ float R[NJ][9];
    __shared__ float J[NJ][3];
    __shared__ float W[NJ][12];

    for (int idx = t; idx < NJ * 3; idx += 32)
        joints[(size_t)b * NJ * 3 + idx] = 0.f;

    if (t < NJ) {
#pragma unroll
        for (int c = 0; c < 3; ++c) {
            float s = g_JrT[t * 3 + c];
#pragma unroll
            for (int k = 0; k < NB; ++k)
                s = fmaf(g_JrS[t * 3 * NB + c * NB + k], betas[b * NB + k], s);
            J[t][c] = s;
        }
        float x = thetas[b * NJ * 3 + t * 3 + 0];
        float y = thetas[b * NJ * 3 + t * 3 + 1];
        float z = thetas[b * NJ * 3 + t * 3 + 2];
        float th = sqrtf(x * x + y * y + z * z) + 1e-8f;
        float rx = x / th, ry = y / th, rz = z / th;
        float cth = cosf(th), sth = sinf(th), ic = 1.f - cth;
        float r[9];
        r[0] = cth + ic * rx * rx;
        r[1] = ic * rx * ry - sth * rz;
        r[2] = ic * rx * rz + sth * ry;
        r[3] = ic * rx * ry + sth * rz;
        r[4] = cth + ic * ry * ry;
        r[5] = ic * ry * rz - sth * rx;
        r[6] = ic * rx * rz - sth * ry;
        r[7] = ic * ry * rz + sth * rx;
        r[8] = cth + ic * rz * rz;
        if (t == 0) {
            float sc = scale[0];
#pragma unroll
            for (int k = 0; k < 9; ++k) r[k] *= sc;
        }
#pragma unroll
        for (int k = 0; k < 9; ++k) R[t][k] = r[k];
    }
    __syncthreads();

    if (t == 0) {
#pragma unroll
        for (int rr = 0; rr < 3; ++rr) {
            W[0][rr * 4 + 0] = R[0][rr * 3 + 0];
            W[0][rr * 4 + 1] = R[0][rr * 3 + 1];
            W[0][rr * 4 + 2] = R[0][rr * 3 + 2];
            W[0][rr * 4 + 3] = J[0][rr];
        }
        for (int i = 1; i < NJ; ++i) {
            int p = c_par[i];
            float tx = J[i][0] - J[p][0];
            float ty = J[i][1] - J[p][1];
            float tz = J[i][2] - J[p][2];
#pragma unroll
            for (int rr = 0; rr < 3; ++rr) {
                float w0 = W[p][rr * 4 + 0], w1 = W[p][rr * 4 + 1],
                      w2 = W[p][rr * 4 + 2], w3 = W[p][rr * 4 + 3];
#pragma unroll
                for (int cc = 0; cc < 3; ++cc)
                    W[i][rr * 4 + cc] = w0 * R[i][0 * 3 + cc] +
                                        w1 * R[i][1 * 3 + cc] +
                                        w2 * R[i][2 * 3 + cc];
                W[i][rr * 4 + 3] = w0 * tx + w1 * ty + w2 * tz + w3;
            }
        }
    }
    __syncthreads();

    if (t < NJ) {
        float* g = g_G + ((size_t)b * NJ + t) * 12;
#pragma unroll
        for (int rr = 0; rr < 3; ++rr) {
            float w0 = W[t][rr * 4 + 0], w1 = W[t][rr * 4 + 1],
                  w2 = W[t][rr * 4 + 2], w3 = W[t][rr * 4 + 3];
            g[rr * 4 + 0] = w0;
            g[rr * 4 + 1] = w1;
            g[rr * 4 + 2] = w2;
            g[rr * 4 + 3] = w3 - (w0 * J[t][0] + w1 * J[t][1] + w2 * J[t][2]);
        }
    }
    for (int idx = t; idx < NP; idx += 32) {
        int j = idx / 9 + 1;
        int rc = idx % 9;
        float v = R[j][rc];
        if (rc == 0 || rc == 4 || rc == 8) v -= 1.f;
        g_lrot[(size_t)b * NP + idx] = v;
    }
}

// ---------------------------------------------------------------------------
// Kernel C: fused shape+pose blend + LBS (R9 config: TB=8, bf16 pd stream).
// ---------------------------------------------------------------------------
__global__ __launch_bounds__(CBLK, 5) void kC(const float* __restrict__ betas,
                                              const float* __restrict__ trans,
                                              float* __restrict__ out, int Btot) {
    __shared__ __align__(16) float lr_sh[NPP][TB];
    __shared__ __align__(16) float2 G2[TBH][NJ][12];
    __shared__ __align__(16) float bet_sh[NB][TB];
    __shared__ __align__(16) float2 tr2[TBH][3];

    int b0 = blockIdx.y * TB;
    int bcnt = Btot - b0; if (bcnt > TB) bcnt = TB;
    int tid = threadIdx.x;

    for (int i = tid; i < NPP * TB; i += CBLK) {
        int p = i / TB, bb = i % TB;
        lr_sh[p][bb] = (p < NP && bb < bcnt)
                           ? g_lrot[(size_t)(b0 + bb) * NP + p] : 0.f;
    }
    for (int i = tid; i < TBH * NJ * 12; i += CBLK) {
        int q = i / (NJ * 12), k = i % (NJ * 12);
        int be = 2 * q, bo = 2 * q + 1;
        float ge = (be < bcnt) ? g_G[(size_t)(b0 + be) * NJ * 12 + k] : 0.f;
        float go = (bo < bcnt) ? g_G[(size_t)(b0 + bo) * NJ * 12 + k] : 0.f;
        G2[q][k / 12][k % 12] = make_float2(ge, go);
    }
    for (int i = tid; i < NB * TB; i += CBLK) {
        int s = i / TB, bb = i % TB;
        bet_sh[s][bb] = (bb < bcnt) ? betas[(b0 + bb) * NB + s] : 0.f;
    }
    for (int i = tid; i < TBH * 3; i += CBLK) {
        int q = i / 3, c = i % 3;
        int be = 2 * q, bo = 2 * q + 1;
        float te = (be < bcnt) ? trans[(b0 + be) * 3 + c] : 0.f;
        float to = (bo < bcnt) ? trans[(b0 + bo) * 3 + c] : 0.f;
        tr2[q][c] = make_float2(te, to);
    }
    __syncthreads();

    int v = blockIdx.x * CBLK + tid;
    int vc = v < NVERT ? v : NVERT - 1;
    bool valid = v < NVERT;

    u64 A0[TBH], A1[TBH], A2[TBH];
    {
        u64 t0 = pack2(__ldg(&g_vtT[0 * NVERT + vc]));
        u64 t1 = pack2(__ldg(&g_vtT[1 * NVERT + vc]));
        u64 t2 = pack2(__ldg(&g_vtT[2 * NVERT + vc]));
#pragma unroll
        for (int q = 0; q < TBH; ++q) { A0[q] = t0; A1[q] = t1; A2[q] = t2; }
    }

#pragma unroll
    for (int s = 0; s < NB; ++s) {
        u64 sa = pack2(__ldg(&g_sdT[(size_t)(0 * NB + s) * NVERT + vc]));
        u64 sb = pack2(__ldg(&g_sdT[(size_t)(1 * NB + s) * NVERT + vc]));
        u64 sc = pack2(__ldg(&g_sdT[(size_t)(2 * NB + s) * NVERT + vc]));
        const ulonglong2* l = reinterpret_cast<const ulonglong2*>(bet_sh[s]);
#pragma unroll
        for (int h = 0; h < TBH / 2; ++h) {
            ulonglong2 lv = l[h];
            A0[2*h]   = fma2(sa, lv.x, A0[2*h]);
            A0[2*h+1] = fma2(sa, lv.y, A0[2*h+1]);
            A1[2*h]   = fma2(sb, lv.x, A1[2*h]);
            A1[2*h+1] = fma2(sb, lv.y, A1[2*h+1]);
            A2[2*h]   = fma2(sc, lv.x, A2[2*h]);
            A2[2*h+1] = fma2(sc, lv.y, A2[2*h+1]);
        }
    }

    const uint4* pq0 = g_pdh4 + (size_t)0 * NP8 * NVERT + vc;
    const uint4* pq1 = g_pdh4 + (size_t)1 * NP8 * NVERT + vc;
    const uint4* pq2 = g_pdh4 + (size_t)2 * NP8 * NVERT + vc;

    uint4 r0a = __ldg(pq0), r0b = __ldg(pq1), r0c = __ldg(pq2);
    uint4 r1a = __ldg(pq0 + NVERT), r1b = __ldg(pq1 + NVERT), r1c = __ldg(pq2 + NVERT);

#pragma unroll 2
    for (int p8 = 0; p8 < NP8; ++p8) {
        uint4 r2a, r2b, r2c;
        if (p8 + 2 < NP8) {
            size_t off = (size_t)(p8 + 2) * NVERT;
            r2a = __ldg(pq0 + off);
            r2b = __ldg(pq1 + off);
            r2c = __ldg(pq2 + off);
        } else {
            r2a = r2b = r2c = make_uint4(0, 0, 0, 0);
        }
#pragma unroll
        for (int w = 0; w < 4; ++w) {
            unsigned ua = (w == 0) ? r0a.x : (w == 1) ? r0a.y : (w == 2) ? r0a.z : r0a.w;
            unsigned ub = (w == 0) ? r0b.x : (w == 1) ? r0b.y : (w == 2) ? r0b.z : r0b.w;
            unsigned uc = (w == 0) ? r0c.x : (w == 1) ? r0c.y : (w == 2) ? r0c.z : r0c.w;
#pragma unroll
            for (int e = 0; e < 2; ++e) {
                u64 pa = e ? splat_hi(ua) : splat_lo(ua);
                u64 pb = e ? splat_hi(ub) : splat_lo(ub);
                u64 pc = e ? splat_hi(uc) : splat_lo(uc);
                const ulonglong2* l =
                    reinterpret_cast<const ulonglong2*>(lr_sh[p8 * 8 + w * 2 + e]);
#pragma unroll
                for (int h = 0; h < TBH / 2; ++h) {
                    ulonglong2 lv = l[h];
                    A0[2*h]   = fma2(pa, lv.x, A0[2*h]);
                    A0[2*h+1] = fma2(pa, lv.y, A0[2*h+1]);
                    A1[2*h]   = fma2(pb, lv.x, A1[2*h]);
                    A1[2*h+1] = fma2(pb, lv.y, A1[2*h+1]);
                    A2[2*h]   = fma2(pc, lv.x, A2[2*h]);
                    A2[2*h+1] = fma2(pc, lv.y, A2[2*h+1]);
                }
            }
        }
        r0a = r1a; r0b = r1b; r0c = r1c;
        r1a = r2a; r1b = r2b; r1c = r2c;
    }

    float wv[NJ];
#pragma unroll
    for (int j = 0; j < NJ; ++j) wv[j] = __ldg(&g_wT[(size_t)j * NVERT + vc]);

#pragma unroll
    for (int q = 0; q < TBH; ++q) {
        u64 T[12];
#pragma unroll
        for (int k = 0; k < 12; ++k) T[k] = 0ull;
        const ulonglong2* gq = reinterpret_cast<const ulonglong2*>(G2[q][0]);
#pragma unroll 4
        for (int j = 0; j < NJ; ++j) {
            u64 wj = pack2(wv[j]);
            const ulonglong2* g = gq + j * 6;
#pragma unroll
            for (int k = 0; k < 6; ++k) {
                ulonglong2 gg = g[k];
                T[2*k]   = fma2(wj, gg.x, T[2*k]);
                T[2*k+1] = fma2(wj, gg.y, T[2*k+1]);
            }
        }
        u64 ox = fma2(T[0], A0[q], fma2(T[1], A1[q], fma2(T[2], A2[q], T[3])));
        u64 oy = fma2(T[4], A0[q], fma2(T[5], A1[q], fma2(T[6], A2[q], T[7])));
        u64 oz = fma2(T[8], A0[q], fma2(T[9], A1[q], fma2(T[10], A2[q], T[11])));
        const u64* tq = reinterpret_cast<const u64*>(tr2[q]);
        ox = add2(ox, tq[0]);
        oy = add2(oy, tq[1]);
        oz = add2(oz, tq[2]);
        float xe, xo, ye, yo, ze, zo;
        unpack2(ox, xe, xo);
        unpack2(oy, ye, yo);
        unpack2(oz, ze, zo);
        int be = 2 * q, bo = 2 * q + 1;
        if (valid && be < bcnt) {
            size_t o = ((size_t)(b0 + be) * NVERT + v) * 3;
            out[o + 0] = xe; out[o + 1] = ye; out[o + 2] = ze;
        }
        if (valid && bo < bcnt) {
            size_t o = ((size_t)(b0 + bo) * NVERT + v) * 3;
            out[o + 0] = xo; out[o + 1] = yo; out[o + 2] = zo;
        }
    }
}

// ---------------------------------------------------------------------------
// Kernel D2: joints += Jr @ result. Block = (16 batches) x (1 vertex split).
// Jr vertex-slice staged ONCE in dynamic smem, reused across 16 batches.
// ---------------------------------------------------------------------------
extern __shared__ float JrS[];   // [NJ][vcnt]

__global__ __launch_bounds__(256) void kD2(const float* __restrict__ Jr,
                                           const float* __restrict__ result,
                                           float* __restrict__ joints, int Btot) {
    int bg = blockIdx.x;
    int sp = blockIdx.y;
    int v0 = sp * VCH;
    int vcnt = NVERT - v0; if (vcnt > VCH) vcnt = VCH;
    int tid = threadIdx.x;

    for (int i = tid; i < NJ * vcnt; i += 256) {
        int j = i / vcnt, vv = i - j * vcnt;
        JrS[i] = Jr[(size_t)j * NVERT + v0 + vv];
    }
    __shared__ float sm[NJ * 3];
    __syncthreads();

    for (int bb = 0; bb < DB; ++bb) {
        int b = bg * DB + bb;
        if (b >= Btot) break;

        float acc[NJ][3];
#pragma unroll
        for (int j = 0; j < NJ; ++j) {
            acc[j][0] = 0.f; acc[j][1] = 0.f; acc[j][2] = 0.f;
        }
        const float* rb = result + ((size_t)b * NVERT + v0) * 3;
        for (int i = tid; i < vcnt; i += 256) {
            float rx = rb[i * 3 + 0], ry = rb[i * 3 + 1], rz = rb[i * 3 + 2];
#pragma unroll
            for (int j = 0; j < NJ; ++j) {
                float w = JrS[j * vcnt + i];
                acc[j][0] = fmaf(w, rx, acc[j][0]);
                acc[j][1] = fmaf(w, ry, acc[j][1]);
                acc[j][2] = fmaf(w, rz, acc[j][2]);
            }
        }

        if (tid < NJ * 3) sm[tid] = 0.f;
        __syncthreads();
#pragma unroll
        for (int j = 0; j < NJ; ++j) {
#pragma unroll
            for (int c = 0; c < 3; ++c) {
                float x = acc[j][c];
#pragma unroll
                for (int off = 16; off > 0; off >>= 1)
                    x += __shfl_xor_sync(0xffffffffu, x, off);
                if ((tid & 31) == 0) atomicAdd(&sm[j * 3 + c], x);
            }
        }
        __syncthreads();
        if (tid < NJ * 3)
            atomicAdd(&joints[(size_t)b * NJ * 3 + tid], sm[tid]);
        __syncthreads();
    }
}

// ---------------------------------------------------------------------------
extern "C" void kernel_launch(void* const* d_in, const int* in_sizes, int n_in,
                              void* d_out, int out_size) {
    const float* betas  = (const float*)d_in[0];
    const float* thetas = (const float*)d_in[1];
    const float* trans  = (const float*)d_in[2];
    const float* scale  = (const float*)d_in[3];
    const float* vt     = (const float*)d_in[4];
    const float* sd     = (const float*)d_in[5];
    const float* pd     = (const float*)d_in[6];
    const float* Jr     = (const float*)d_in[7];
    const float* wgt    = (const float*)d_in[8];

    int Btot = in_sizes[0] / NB;
    float* out = (float*)d_out;
    float* joints = out + (size_t)Btot * NVERT * 3;

    dim3 tb(32, 8);
    dim3 gpd((NPP + 31) / 32, (NVERT + 31) / 32, 3);
    kTpd<<<gpd, tb>>>(pd);
    dim3 g3((NVERT + 31) / 32, 1, 3);
    kT3<<<g3, tb>>>(wgt, sd, vt);

    kA<<<NJ, 256>>>(Jr);
    kB<<<Btot, 32>>>(betas, thetas, scale, joints);

    dim3 gc((NVERT + CBLK - 1) / CBLK, (Btot + TB - 1) / TB);
    kC<<<gc, CBLK>>>(betas, trans, out, Btot);

    int jrBytes = NJ * VCH * 4;   // 82,752 B
    static int attr_set = 0;
    if (!attr_set) {
        cudaFuncSetAttribute(kD2, cudaFuncAttributeMaxDynamicSharedMemorySize,
                             jrBytes);
        attr_set = 1;
    }
    dim3 gd((Btot + DB - 1) / DB, VSPL);
    kD2<<<gd, 256, jrBytes>>>(Jr, out, joints, Btot);
}

// round 15
// speedup vs baseline: 1.0532x; 1.0532x over previous
#include <cuda_runtime.h>
#include <cuda_bf16.h>

#define NVERT 6890
#define NJ 24
#define NB 10
#define NP 207
#define NP8 26
#define NPP (NP8*8)
#define MAXB 1024
#define TB 8
#define TBH 4
#define CBLK 128
#define VSPL 8
#define VCH 862
#define BWB 8            // batches per kB block

typedef unsigned long long u64;

__device__ __forceinline__ u64 pack2(float x) {
    u64 r; asm("mov.b64 %0,{%1,%1};" : "=l"(r) : "f"(x)); return r;
}
__device__ __forceinline__ void unpack2(u64 v, float& a, float& b) {
    asm("mov.b64 {%0,%1},%2;" : "=f"(a), "=f"(b) : "l"(v));
}
__device__ __forceinline__ u64 fma2(u64 a, u64 b, u64 c) {
    u64 d; asm("fma.rn.f32x2 %0,%1,%2,%3;" : "=l"(d) : "l"(a), "l"(b), "l"(c)); return d;
}
__device__ __forceinline__ u64 add2(u64 a, u64 b) {
    u64 d; asm("add.rn.f32x2 %0,%1,%2;" : "=l"(d) : "l"(a), "l"(b)); return d;
}
__device__ __forceinline__ u64 splat_lo(unsigned u) {
    unsigned f = u << 16;
    u64 r; asm("mov.b64 %0,{%1,%1};" : "=l"(r) : "r"(f)); return r;
}
__device__ __forceinline__ u64 splat_hi(unsigned u) {
    unsigned f = u & 0xffff0000u;
    u64 r; asm("mov.b64 %0,{%1,%1};" : "=l"(r) : "r"(f)); return r;
}

__constant__ int c_par[NJ] = {-1, 0, 0, 0, 1, 2, 3, 4, 5, 6, 7, 8, 9, 9, 9,
                              12, 13, 14, 16, 17, 18, 19, 20, 21};

__device__ float g_JrT[NJ * 3];
__device__ float g_JrS[NJ * 3 * NB];
__device__ float g_G[MAXB * NJ * 12];
__device__ float g_lrot[MAXB * NP];

__device__ uint4 g_pdh4[(size_t)3 * NP8 * NVERT];
__device__ float g_sdT[3 * NB * NVERT];
__device__ float g_wT[NJ * NVERT];
__device__ float g_vtT[3 * NVERT];

// ---------------------------------------------------------------------------
// kT: ALL transposes in one launch.
// z<3: pd coord c=z -> g_pdh4 bf16-packed. z=3..5 (y==0 only): wgt/sd/vt.
// grid = (216, 7, 6), block (32,8)
// ---------------------------------------------------------------------------
__global__ __launch_bounds__(256) void kT(const float* __restrict__ pd,
                                          const float* __restrict__ wgt,
                                          const float* __restrict__ sd,
                                          const float* __restrict__ vt) {
    __shared__ float tile[32][33];
    int z = blockIdx.z;
    if (z < 3) {
        int c = z;
        int p0 = blockIdx.y * 32, v0 = blockIdx.x * 32;
        for (int r = threadIdx.y; r < 32; r += 8) {
            int v = v0 + r, p = p0 + threadIdx.x;
            tile[r][threadIdx.x] =
                (v < NVERT && p < NP) ? pd[((size_t)v * 3 + c) * NP + p] : 0.f;
        }
        __syncthreads();
        int p8l = threadIdx.y;
        int vl = threadIdx.x;
        if (p8l < 4) {
            int p8g = blockIdx.y * 4 + p8l;
            int v = v0 + vl;
            if (p8g < NP8 && v < NVERT) {
                unsigned w[4];
#pragma unroll
                for (int k = 0; k < 4; ++k) {
                    float f0 = tile[vl][p8l * 8 + 2 * k + 0];
                    float f1 = tile[vl][p8l * 8 + 2 * k + 1];
                    unsigned lo = __bfloat16_as_ushort(__float2bfloat16(f0));
                    unsigned hi = __bfloat16_as_ushort(__float2bfloat16(f1));
                    w[k] = lo | (hi << 16);
                }
                g_pdh4[((size_t)c * NP8 + p8g) * NVERT + v] =
                    make_uint4(w[0], w[1], w[2], w[3]);
            }
        }
    } else {
        if (blockIdx.y != 0) return;
        const float* in; float* out; int K;
        if (z == 3)      { in = wgt; out = g_wT;  K = NJ; }
        else if (z == 4) { in = sd;  out = g_sdT; K = 3 * NB; }
        else             { in = vt;  out = g_vtT; K = 3; }
        int v0 = blockIdx.x * 32;
        for (int r = threadIdx.y; r < 32; r += 8) {
            int v = v0 + r, k = threadIdx.x;
            tile[r][k] = (v < NVERT && k < K) ? in[(size_t)v * K + k] : 0.f;
        }
        __syncthreads();
        for (int r = threadIdx.y; r < 32; r += 8) {
            int k = r, v = v0 + threadIdx.x;
            if (k < K && v < NVERT) out[(size_t)k * NVERT + v] = tile[threadIdx.x][r];
        }
    }
}

// ---------------------------------------------------------------------------
// Kernel A: fold J_regressor into v_template and shapedirs (raw input reads).
// ---------------------------------------------------------------------------
__global__ __launch_bounds__(256) void kA(const float* __restrict__ Jr,
                                          const float* __restrict__ vt,
                                          const float* __restrict__ sd) {
    int j = blockIdx.x;
    float acc[33];
#pragma unroll
    for (int k = 0; k < 33; ++k) acc[k] = 0.f;

    for (int v = threadIdx.x; v < NVERT; v += blockDim.x) {
        float w = Jr[j * NVERT + v];
        const float* vtp = vt + v * 3;
        const float* sdp = sd + (size_t)v * 3 * NB;
        acc[0] = fmaf(w, __ldg(vtp + 0), acc[0]);
        acc[1] = fmaf(w, __ldg(vtp + 1), acc[1]);
        acc[2] = fmaf(w, __ldg(vtp + 2), acc[2]);
#pragma unroll
        for (int k = 0; k < 3 * NB; ++k)
            acc[3 + k] = fmaf(w, __ldg(sdp + k), acc[3 + k]);
    }
#pragma unroll
    for (int k = 0; k < 33; ++k) {
#pragma unroll
        for (int off = 16; off > 0; off >>= 1)
            acc[k] += __shfl_xor_sync(0xffffffffu, acc[k], off);
    }
    __shared__ float sm[33];
    if (threadIdx.x < 33) sm[threadIdx.x] = 0.f;
    __syncthreads();
    if ((threadIdx.x & 31) == 0) {
#pragma unroll
        for (int k = 0; k < 33; ++k) atomicAdd(&sm[k], acc[k]);
    }
    __syncthreads();
    // raw sd layout is [v][c][s] -> sm[3+k] with k = c*NB+s matches g_JrS[j][c][s]
    if (threadIdx.x < 3) g_JrT[j * 3 + threadIdx.x] = sm[threadIdx.x];
    if (threadIdx.x >= 3 && threadIdx.x < 33)
        g_JrS[j * 3 * NB + threadIdx.x - 3] = sm[threadIdx.x];
}

// ---------------------------------------------------------------------------
// Kernel B: 8 batches per block, one warp each. Warp-private smem slices.
// ---------------------------------------------------------------------------
__global__ __launch_bounds__(32 * BWB) void kB(const float* __restrict__ betas,
                                               const float* __restrict__ thetas,
                                               const float* __restrict__ scale,
                                               float* __restrict__ joints,
                                               int Btot) {
    int w = threadIdx.x >> 5;
    int t = threadIdx.x & 31;
    int b = blockIdx.x * BWB + w;
    if (b >= Btot) return;

    __shared__ float R[BWB][NJ][9];
    __shared__ float J[BWB][NJ][3];
    __shared__ float W[BWB][NJ][12];

    for (int idx = t; idx < NJ * 3; idx += 32)
        joints[(size_t)b * NJ * 3 + idx] = 0.f;

    if (t < NJ) {
#pragma unroll
        for (int c = 0; c < 3; ++c) {
            float s = g_JrT[t * 3 + c];
#pragma unroll
            for (int k = 0; k < NB; ++k)
                s = fmaf(g_JrS[t * 3 * NB + c * NB + k], betas[b * NB + k], s);
            J[w][t][c] = s;
        }
        float x = thetas[b * NJ * 3 + t * 3 + 0];
        float y = thetas[b * NJ * 3 + t * 3 + 1];
        float z = thetas[b * NJ * 3 + t * 3 + 2];
        float th = sqrtf(x * x + y * y + z * z) + 1e-8f;
        float rx = x / th, ry = y / th, rz = z / th;
        float cth = cosf(th), sth = sinf(th), ic = 1.f - cth;
        float r[9];
        r[0] = cth + ic * rx * rx;
        r[1] = ic * rx * ry - sth * rz;
        r[2] = ic * rx * rz + sth * ry;
        r[3] = ic * rx * ry + sth * rz;
        r[4] = cth + ic * ry * ry;
        r[5] = ic * ry * rz - sth * rx;
        r[6] = ic * rx * rz - sth * ry;
        r[7] = ic * ry * rz + sth * rx;
        r[8] = cth + ic * rz * rz;
        if (t == 0) {
            float sc = scale[0];
#pragma unroll
            for (int k = 0; k < 9; ++k) r[k] *= sc;
        }
#pragma unroll
        for (int k = 0; k < 9; ++k) R[w][t][k] = r[k];
    }
    __syncwarp();

    if (t == 0) {
#pragma unroll
        for (int rr = 0; rr < 3; ++rr) {
            W[w][0][rr * 4 + 0] = R[w][0][rr * 3 + 0];
            W[w][0][rr * 4 + 1] = R[w][0][rr * 3 + 1];
            W[w][0][rr * 4 + 2] = R[w][0][rr * 3 + 2];
            W[w][0][rr * 4 + 3] = J[w][0][rr];
        }
        for (int i = 1; i < NJ; ++i) {
            int p = c_par[i];
            float tx = J[w][i][0] - J[w][p][0];
            float ty = J[w][i][1] - J[w][p][1];
            float tz = J[w][i][2] - J[w][p][2];
#pragma unroll
            for (int rr = 0; rr < 3; ++rr) {
                float w0 = W[w][p][rr * 4 + 0], w1 = W[w][p][rr * 4 + 1],
                      w2 = W[w][p][rr * 4 + 2], w3 = W[w][p][rr * 4 + 3];
#pragma unroll
                for (int cc = 0; cc < 3; ++cc)
                    W[w][i][rr * 4 + cc] = w0 * R[w][i][0 * 3 + cc] +
                                           w1 * R[w][i][1 * 3 + cc] +
                                           w2 * R[w][i][2 * 3 + cc];
                W[w][i][rr * 4 + 3] = w0 * tx + w1 * ty + w2 * tz + w3;
            }
        }
    }
    __syncwarp();

    if (t < NJ) {
        float* g = g_G + ((size_t)b * NJ + t) * 12;
#pragma unroll
        for (int rr = 0; rr < 3; ++rr) {
            float w0 = W[w][t][rr * 4 + 0], w1 = W[w][t][rr * 4 + 1],
                  w2 = W[w][t][rr * 4 + 2], w3 = W[w][t][rr * 4 + 3];
            g[rr * 4 + 0] = w0;
            g[rr * 4 + 1] = w1;
            g[rr * 4 + 2] = w2;
            g[rr * 4 + 3] = w3 - (w0 * J[w][t][0] + w1 * J[w][t][1] + w2 * J[w][t][2]);
        }
    }
    for (int idx = t; idx < NP; idx += 32) {
        int j = idx / 9 + 1;
        int rc = idx % 9;
        float v = R[w][j][rc];
        if (rc == 0 || rc == 4 || rc == 8) v -= 1.f;
        g_lrot[(size_t)b * NP + idx] = v;
    }
}

// ---------------------------------------------------------------------------
// Kernel C: fused shape+pose blend + LBS (R9-exact).
// ---------------------------------------------------------------------------
__global__ __launch_bounds__(CBLK, 5) void kC(const float* __restrict__ betas,
                                              const float* __restrict__ trans,
                                              float* __restrict__ out, int Btot) {
    __shared__ __align__(16) float lr_sh[NPP][TB];
    __shared__ __align__(16) float2 G2[TBH][NJ][12];
    __shared__ __align__(16) float bet_sh[NB][TB];
    __shared__ __align__(16) float2 tr2[TBH][3];

    int b0 = blockIdx.y * TB;
    int bcnt = Btot - b0; if (bcnt > TB) bcnt = TB;
    int tid = threadIdx.x;

    for (int i = tid; i < NPP * TB; i += CBLK) {
        int p = i / TB, bb = i % TB;
        lr_sh[p][bb] = (p < NP && bb < bcnt)
                           ? g_lrot[(size_t)(b0 + bb) * NP + p] : 0.f;
    }
    for (int i = tid; i < TBH * NJ * 12; i += CBLK) {
        int q = i / (NJ * 12), k = i % (NJ * 12);
        int be = 2 * q, bo = 2 * q + 1;
        float ge = (be < bcnt) ? g_G[(size_t)(b0 + be) * NJ * 12 + k] : 0.f;
        float go = (bo < bcnt) ? g_G[(size_t)(b0 + bo) * NJ * 12 + k] : 0.f;
        G2[q][k / 12][k % 12] = make_float2(ge, go);
    }
    for (int i = tid; i < NB * TB; i += CBLK) {
        int s = i / TB, bb = i % TB;
        bet_sh[s][bb] = (bb < bcnt) ? betas[(b0 + bb) * NB + s] : 0.f;
    }
    for (int i = tid; i < TBH * 3; i += CBLK) {
        int q = i / 3, c = i % 3;
        int be = 2 * q, bo = 2 * q + 1;
        float te = (be < bcnt) ? trans[(b0 + be) * 3 + c] : 0.f;
        float to = (bo < bcnt) ? trans[(b0 + bo) * 3 + c] : 0.f;
        tr2[q][c] = make_float2(te, to);
    }
    __syncthreads();

    int v = blockIdx.x * CBLK + tid;
    int vc = v < NVERT ? v : NVERT - 1;
    bool valid = v < NVERT;

    u64 A0[TBH], A1[TBH], A2[TBH];
    {
        u64 t0 = pack2(__ldg(&g_vtT[0 * NVERT + vc]));
        u64 t1 = pack2(__ldg(&g_vtT[1 * NVERT + vc]));
        u64 t2 = pack2(__ldg(&g_vtT[2 * NVERT + vc]));
#pragma unroll
        for (int q = 0; q < TBH; ++q) { A0[q] = t0; A1[q] = t1; A2[q] = t2; }
    }

#pragma unroll
    for (int s = 0; s < NB; ++s) {
        u64 sa = pack2(__ldg(&g_sdT[(size_t)(0 * NB + s) * NVERT + vc]));
        u64 sb = pack2(__ldg(&g_sdT[(size_t)(1 * NB + s) * NVERT + vc]));
        u64 sc = pack2(__ldg(&g_sdT[(size_t)(2 * NB + s) * NVERT + vc]));
        const ulonglong2* l = reinterpret_cast<const ulonglong2*>(bet_sh[s]);
#pragma unroll
        for (int h = 0; h < TBH / 2; ++h) {
            ulonglong2 lv = l[h];
            A0[2*h]   = fma2(sa, lv.x, A0[2*h]);
            A0[2*h+1] = fma2(sa, lv.y, A0[2*h+1]);
            A1[2*h]   = fma2(sb, lv.x, A1[2*h]);
            A1[2*h+1] = fma2(sb, lv.y, A1[2*h+1]);
            A2[2*h]   = fma2(sc, lv.x, A2[2*h]);
            A2[2*h+1] = fma2(sc, lv.y, A2[2*h+1]);
        }
    }

    const uint4* pq0 = g_pdh4 + (size_t)0 * NP8 * NVERT + vc;
    const uint4* pq1 = g_pdh4 + (size_t)1 * NP8 * NVERT + vc;
    const uint4* pq2 = g_pdh4 + (size_t)2 * NP8 * NVERT + vc;

    uint4 r0a = __ldg(pq0), r0b = __ldg(pq1), r0c = __ldg(pq2);
    uint4 r1a = __ldg(pq0 + NVERT), r1b = __ldg(pq1 + NVERT), r1c = __ldg(pq2 + NVERT);

    for (int p8 = 0; p8 < NP8; ++p8) {
        uint4 r2a, r2b, r2c;
        if (p8 + 2 < NP8) {
            size_t off = (size_t)(p8 + 2) * NVERT;
            r2a = __ldg(pq0 + off);
            r2b = __ldg(pq1 + off);
            r2c = __ldg(pq2 + off);
        } else {
            r2a = r2b = r2c = make_uint4(0, 0, 0, 0);
        }
#pragma unroll
        for (int w = 0; w < 4; ++w) {
            unsigned ua = (w == 0) ? r0a.x : (w == 1) ? r0a.y : (w == 2) ? r0a.z : r0a.w;
            unsigned ub = (w == 0) ? r0b.x : (w == 1) ? r0b.y : (w == 2) ? r0b.z : r0b.w;
            unsigned uc = (w == 0) ? r0c.x : (w == 1) ? r0c.y : (w == 2) ? r0c.z : r0c.w;
#pragma unroll
            for (int e = 0; e < 2; ++e) {
                u64 pa = e ? splat_hi(ua) : splat_lo(ua);
                u64 pb = e ? splat_hi(ub) : splat_lo(ub);
                u64 pc = e ? splat_hi(uc) : splat_lo(uc);
                const ulonglong2* l =
                    reinterpret_cast<const ulonglong2*>(lr_sh[p8 * 8 + w * 2 + e]);
#pragma unroll
                for (int h = 0; h < TBH / 2; ++h) {
                    ulonglong2 lv = l[h];
                    A0[2*h]   = fma2(pa, lv.x, A0[2*h]);
                    A0[2*h+1] = fma2(pa, lv.y, A0[2*h+1]);
                    A1[2*h]   = fma2(pb, lv.x, A1[2*h]);
                    A1[2*h+1] = fma2(pb, lv.y, A1[2*h+1]);
                    A2[2*h]   = fma2(pc, lv.x, A2[2*h]);
                    A2[2*h+1] = fma2(pc, lv.y, A2[2*h+1]);
                }
            }
        }
        r0a = r1a; r0b = r1b; r0c = r1c;
        r1a = r2a; r1b = r2b; r1c = r2c;
    }

    float wv[NJ];
#pragma unroll
    for (int j = 0; j < NJ; ++j) wv[j] = __ldg(&g_wT[(size_t)j * NVERT + vc]);

#pragma unroll
    for (int q = 0; q < TBH; ++q) {
        u64 T[12];
#pragma unroll
        for (int k = 0; k < 12; ++k) T[k] = 0ull;
        const ulonglong2* gq = reinterpret_cast<const ulonglong2*>(G2[q][0]);
#pragma unroll 4
        for (int j = 0; j < NJ; ++j) {
            u64 wj = pack2(wv[j]);
            const ulonglong2* g = gq + j * 6;
#pragma unroll
            for (int k = 0; k < 6; ++k) {
                ulonglong2 gg = g[k];
                T[2*k]   = fma2(wj, gg.x, T[2*k]);
                T[2*k+1] = fma2(wj, gg.y, T[2*k+1]);
            }
        }
        u64 ox = fma2(T[0], A0[q], fma2(T[1], A1[q], fma2(T[2], A2[q], T[3])));
        u64 oy = fma2(T[4], A0[q], fma2(T[5], A1[q], fma2(T[6], A2[q], T[7])));
        u64 oz = fma2(T[8], A0[q], fma2(T[9], A1[q], fma2(T[10], A2[q], T[11])));
        const u64* tq = reinterpret_cast<const u64*>(tr2[q]);
        ox = add2(ox, tq[0]);
        oy = add2(oy, tq[1]);
        oz = add2(oz, tq[2]);
        float xe, xo, ye, yo, ze, zo;
        unpack2(ox, xe, xo);
        unpack2(oy, ye, yo);
        unpack2(oz, ze, zo);
        int be = 2 * q, bo = 2 * q + 1;
        if (valid && be < bcnt) {
            size_t o = ((size_t)(b0 + be) * NVERT + v) * 3;
            out[o + 0] = xe; out[o + 1] = ye; out[o + 2] = ze;
        }
        if (valid && bo < bcnt) {
            size_t o = ((size_t)(b0 + bo) * NVERT + v) * 3;
            out[o + 0] = xo; out[o + 1] = yo; out[o + 2] = zo;
        }
    }
}

// ---------------------------------------------------------------------------
// Kernel D: joints = J_regressor @ result, grid (B, VSPL), atomic finish.
// ---------------------------------------------------------------------------
__global__ __launch_bounds__(256) void kD(const float* __restrict__ Jr,
                                          const float* __restrict__ result,
                                          float* __restrict__ joints) {
    int b = blockIdx.x;
    int sp = blockIdx.y;
    int v0 = sp * VCH;
    int v1 = v0 + VCH; if (v1 > NVERT) v1 = NVERT;

    float acc[NJ][3];
#pragma unroll
    for (int j = 0; j < NJ; ++j) { acc[j][0] = 0.f; acc[j][1] = 0.f; acc[j][2] = 0.f; }

    const float* rb = result + (size_t)b * NVERT * 3;
    for (int v = v0 + threadIdx.x; v < v1; v += 256) {
        float rx = rb[v * 3 + 0], ry = rb[v * 3 + 1], rz = rb[v * 3 + 2];
#pragma unroll
        for (int j = 0; j < NJ; ++j) {
            float w = __ldg(&Jr[j * NVERT + v]);
            acc[j][0] = fmaf(w, rx, acc[j][0]);
            acc[j][1] = fmaf(w, ry, acc[j][1]);
            acc[j][2] = fmaf(w, rz, acc[j][2]);
        }
    }
    __shared__ float sm[NJ * 3];
    if (threadIdx.x < NJ * 3) sm[threadIdx.x] = 0.f;
    __syncthreads();
#pragma unroll
    for (int j = 0; j < NJ; ++j) {
#pragma unroll
        for (int c = 0; c < 3; ++c) {
            float x = acc[j][c];
#pragma unroll
            for (int off = 16; off > 0; off >>= 1)
                x += __shfl_xor_sync(0xffffffffu, x, off);
            if ((threadIdx.x & 31) == 0) atomicAdd(&sm[j * 3 + c], x);
        }
    }
    __syncthreads();
    if (threadIdx.x < NJ * 3)
        atomicAdd(&joints[(size_t)b * NJ * 3 + threadIdx.x], sm[threadIdx.x]);
}

// ---------------------------------------------------------------------------
extern "C" void kernel_launch(void* const* d_in, const int* in_sizes, int n_in,
                              void* d_out, int out_size) {
    const float* betas  = (const float*)d_in[0];
    const float* thetas = (const float*)d_in[1];
    const float* trans  = (const float*)d_in[2];
    const float* scale  = (const float*)d_in[3];
    const float* vt     = (const float*)d_in[4];
    const float* sd     = (const float*)d_in[5];
    const float* pd     = (const float*)d_in[6];
    const float* Jr     = (const float*)d_in[7];
    const float* wgt    = (const float*)d_in[8];

    int Btot = in_sizes[0] / NB;
    float* out = (float*)d_out;
    float* joints = out + (size_t)Btot * NVERT * 3;

    dim3 tb(32, 8);
    dim3 gT((NVERT + 31) / 32, (NPP + 31) / 32, 6);
    kT<<<gT, tb>>>(pd, wgt, sd, vt);

    kA<<<NJ, 256>>>(Jr, vt, sd);
    kB<<<(Btot + BWB - 1) / BWB, 32 * BWB>>>(betas, thetas, scale, joints, Btot);

    dim3 gc((NVERT + CBLK - 1) / CBLK, (Btot + TB - 1) / TB);
    kC<<<gc, CBLK>>>(betas, trans, out, Btot);

    dim3 gd(Btot, VSPL);
    kD<<<gd, 256>>>(Jr, out, joints);
}

// round 16
// speedup vs baseline: 1.0577x; 1.0043x over previous
#include <cuda_runtime.h>
#include <cuda_bf16.h>

#define NVERT 6890
#define NJ 24
#define NB 10
#define NP 207
#define NP8 26
#define NPP (NP8*8)
#define MAXB 1024
#define TB 8
#define TBH 4
#define CBLK 128
#define VSPL 8
#define VCH 862
#define BWB 8            // batches per kB block

typedef unsigned long long u64;

__device__ __forceinline__ u64 pack2(float x) {
    u64 r; asm("mov.b64 %0,{%1,%1};" : "=l"(r) : "f"(x)); return r;
}
__device__ __forceinline__ void unpack2(u64 v, float& a, float& b) {
    asm("mov.b64 {%0,%1},%2;" : "=f"(a), "=f"(b) : "l"(v));
}
__device__ __forceinline__ u64 fma2(u64 a, u64 b, u64 c) {
    u64 d; asm("fma.rn.f32x2 %0,%1,%2,%3;" : "=l"(d) : "l"(a), "l"(b), "l"(c)); return d;
}
__device__ __forceinline__ u64 add2(u64 a, u64 b) {
    u64 d; asm("add.rn.f32x2 %0,%1,%2;" : "=l"(d) : "l"(a), "l"(b)); return d;
}
__device__ __forceinline__ u64 splat_lo(unsigned u) {
    unsigned f = u << 16;
    u64 r; asm("mov.b64 %0,{%1,%1};" : "=l"(r) : "r"(f)); return r;
}
__device__ __forceinline__ u64 splat_hi(unsigned u) {
    unsigned f = u & 0xffff0000u;
    u64 r; asm("mov.b64 %0,{%1,%1};" : "=l"(r) : "r"(f)); return r;
}

__constant__ int c_par[NJ] = {-1, 0, 0, 0, 1, 2, 3, 4, 5, 6, 7, 8, 9, 9, 9,
                              12, 13, 14, 16, 17, 18, 19, 20, 21};

__device__ float g_JrT[NJ * 3];
__device__ float g_JrS[NJ * 3 * NB];
__device__ float g_G[MAXB * NJ * 12];
__device__ float g_lrot[MAXB * NP];

__device__ uint4 g_pdh4[(size_t)3 * NP8 * NVERT];
__device__ float g_sdT[3 * NB * NVERT];
__device__ float g_wT[NJ * NVERT];
__device__ float g_vtT[3 * NVERT];

// ---------------------------------------------------------------------------
// kT: ALL transposes in one launch.
// z<3: pd coord c=z -> g_pdh4 bf16-packed. z=3..5 (y==0 only): wgt/sd/vt.
// grid = (216, 7, 6), block (32,8)
// ---------------------------------------------------------------------------
__global__ __launch_bounds__(256) void kT(const float* __restrict__ pd,
                                          const float* __restrict__ wgt,
                                          const float* __restrict__ sd,
                                          const float* __restrict__ vt) {
    __shared__ float tile[32][33];
    int z = blockIdx.z;
    if (z < 3) {
        int c = z;
        int p0 = blockIdx.y * 32, v0 = blockIdx.x * 32;
        for (int r = threadIdx.y; r < 32; r += 8) {
            int v = v0 + r, p = p0 + threadIdx.x;
            tile[r][threadIdx.x] =
                (v < NVERT && p < NP) ? pd[((size_t)v * 3 + c) * NP + p] : 0.f;
        }
        __syncthreads();
        int p8l = threadIdx.y;
        int vl = threadIdx.x;
        if (p8l < 4) {
            int p8g = blockIdx.y * 4 + p8l;
            int v = v0 + vl;
            if (p8g < NP8 && v < NVERT) {
                unsigned w[4];
#pragma unroll
                for (int k = 0; k < 4; ++k) {
                    float f0 = tile[vl][p8l * 8 + 2 * k + 0];
                    float f1 = tile[vl][p8l * 8 + 2 * k + 1];
                    unsigned lo = __bfloat16_as_ushort(__float2bfloat16(f0));
                    unsigned hi = __bfloat16_as_ushort(__float2bfloat16(f1));
                    w[k] = lo | (hi << 16);
                }
                g_pdh4[((size_t)c * NP8 + p8g) * NVERT + v] =
                    make_uint4(w[0], w[1], w[2], w[3]);
            }
        }
    } else {
        if (blockIdx.y != 0) return;
        const float* in; float* out; int K;
        if (z == 3)      { in = wgt; out = g_wT;  K = NJ; }
        else if (z == 4) { in = sd;  out = g_sdT; K = 3 * NB; }
        else             { in = vt;  out = g_vtT; K = 3; }
        int v0 = blockIdx.x * 32;
        for (int r = threadIdx.y; r < 32; r += 8) {
            int v = v0 + r, k = threadIdx.x;
            tile[r][k] = (v < NVERT && k < K) ? in[(size_t)v * K + k] : 0.f;
        }
        __syncthreads();
        for (int r = threadIdx.y; r < 32; r += 8) {
            int k = r, v = v0 + threadIdx.x;
            if (k < K && v < NVERT) out[(size_t)k * NVERT + v] = tile[threadIdx.x][r];
        }
    }
}

// ---------------------------------------------------------------------------
// Kernel A: fold J_regressor into v_template and shapedirs (raw input reads).
// ---------------------------------------------------------------------------
__global__ __launch_bounds__(256) void kA(const float* __restrict__ Jr,
                                          const float* __restrict__ vt,
                                          const float* __restrict__ sd) {
    int j = blockIdx.x;
    float acc[33];
#pragma unroll
    for (int k = 0; k < 33; ++k) acc[k] = 0.f;

    for (int v = threadIdx.x; v < NVERT; v += blockDim.x) {
        float w = Jr[j * NVERT + v];
        const float* vtp = vt + v * 3;
        const float* sdp = sd + (size_t)v * 3 * NB;
        acc[0] = fmaf(w, __ldg(vtp + 0), acc[0]);
        acc[1] = fmaf(w, __ldg(vtp + 1), acc[1]);
        acc[2] = fmaf(w, __ldg(vtp + 2), acc[2]);
#pragma unroll
        for (int k = 0; k < 3 * NB; ++k)
            acc[3 + k] = fmaf(w, __ldg(sdp + k), acc[3 + k]);
    }
#pragma unroll
    for (int k = 0; k < 33; ++k) {
#pragma unroll
        for (int off = 16; off > 0; off >>= 1)
            acc[k] += __shfl_xor_sync(0xffffffffu, acc[k], off);
    }
    __shared__ float sm[33];
    if (threadIdx.x < 33) sm[threadIdx.x] = 0.f;
    __syncthreads();
    if ((threadIdx.x & 31) == 0) {
#pragma unroll
        for (int k = 0; k < 33; ++k) atomicAdd(&sm[k], acc[k]);
    }
    __syncthreads();
    // raw sd layout is [v][c][s] -> sm[3+k] with k = c*NB+s matches g_JrS[j][c][s]
    if (threadIdx.x < 3) g_JrT[j * 3 + threadIdx.x] = sm[threadIdx.x];
    if (threadIdx.x >= 3 && threadIdx.x < 33)
        g_JrS[j * 3 * NB + threadIdx.x - 3] = sm[threadIdx.x];
}

// ---------------------------------------------------------------------------
// Kernel B: 8 batches per block, one warp each. Warp-private smem slices.
// ---------------------------------------------------------------------------
__global__ __launch_bounds__(32 * BWB) void kB(const float* __restrict__ betas,
                                               const float* __restrict__ thetas,
                                               const float* __restrict__ scale,
                                               float* __restrict__ joints,
                                               int Btot) {
    int w = threadIdx.x >> 5;
    int t = threadIdx.x & 31;
    int b = blockIdx.x * BWB + w;
    if (b >= Btot) return;

    __shared__ float R[BWB][NJ][9];
    __shared__ float J[BWB][NJ][3];
    __shared__ float W[BWB][NJ][12];

    for (int idx = t; idx < NJ * 3; idx += 32)
        joints[(size_t)b * NJ * 3 + idx] = 0.f;

    if (t < NJ) {
#pragma unroll
        for (int c = 0; c < 3; ++c) {
            float s = g_JrT[t * 3 + c];
#pragma unroll
            for (int k = 0; k < NB; ++k)
                s = fmaf(g_JrS[t * 3 * NB + c * NB + k], betas[b * NB + k], s);
            J[w][t][c] = s;
        }
        float x = thetas[b * NJ * 3 + t * 3 + 0];
        float y = thetas[b * NJ * 3 + t * 3 + 1];
        float z = thetas[b * NJ * 3 + t * 3 + 2];
        float th = sqrtf(x * x + y * y + z * z) + 1e-8f;
        float rx = x / th, ry = y / th, rz = z / th;
        float cth = cosf(th), sth = sinf(th), ic = 1.f - cth;
        float r[9];
        r[0] = cth + ic * rx * rx;
        r[1] = ic * rx * ry - sth * rz;
        r[2] = ic * rx * rz + sth * ry;
        r[3] = ic * rx * ry + sth * rz;
        r[4] = cth + ic * ry * ry;
        r[5] = ic * ry * rz - sth * rx;
        r[6] = ic * rx * rz - sth * ry;
        r[7] = ic * ry * rz + sth * rx;
        r[8] = cth + ic * rz * rz;
        if (t == 0) {
            float sc = scale[0];
#pragma unroll
            for (int k = 0; k < 9; ++k) r[k] *= sc;
        }
#pragma unroll
        for (int k = 0; k < 9; ++k) R[w][t][k] = r[k];
    }
    __syncwarp();

    if (t == 0) {
#pragma unroll
        for (int rr = 0; rr < 3; ++rr) {
            W[w][0][rr * 4 + 0] = R[w][0][rr * 3 + 0];
            W[w][0][rr * 4 + 1] = R[w][0][rr * 3 + 1];
            W[w][0][rr * 4 + 2] = R[w][0][rr * 3 + 2];
            W[w][0][rr * 4 + 3] = J[w][0][rr];
        }
        for (int i = 1; i < NJ; ++i) {
            int p = c_par[i];
            float tx = J[w][i][0] - J[w][p][0];
            float ty = J[w][i][1] - J[w][p][1];
            float tz = J[w][i][2] - J[w][p][2];
#pragma unroll
            for (int rr = 0; rr < 3; ++rr) {
                float w0 = W[w][p][rr * 4 + 0], w1 = W[w][p][rr * 4 + 1],
                      w2 = W[w][p][rr * 4 + 2], w3 = W[w][p][rr * 4 + 3];
#pragma unroll
                for (int cc = 0; cc < 3; ++cc)
                    W[w][i][rr * 4 + cc] = w0 * R[w][i][0 * 3 + cc] +
                                           w1 * R[w][i][1 * 3 + cc] +
                                           w2 * R[w][i][2 * 3 + cc];
                W[w][i][rr * 4 + 3] = w0 * tx + w1 * ty + w2 * tz + w3;
            }
        }
    }
    __syncwarp();

    if (t < NJ) {
        float* g = g_G + ((size_t)b * NJ + t) * 12;
#pragma unroll
        for (int rr = 0; rr < 3; ++rr) {
            float w0 = W[w][t][rr * 4 + 0], w1 = W[w][t][rr * 4 + 1],
                  w2 = W[w][t][rr * 4 + 2], w3 = W[w][t][rr * 4 + 3];
            g[rr * 4 + 0] = w0;
            g[rr * 4 + 1] = w1;
            g[rr * 4 + 2] = w2;
            g[rr * 4 + 3] = w3 - (w0 * J[w][t][0] + w1 * J[w][t][1] + w2 * J[w][t][2]);
        }
    }
    for (int idx = t; idx < NP; idx += 32) {
        int j = idx / 9 + 1;
        int rc = idx % 9;
        float v = R[w][j][rc];
        if (rc == 0 || rc == 4 || rc == 8) v -= 1.f;
        g_lrot[(size_t)b * NP + idx] = v;
    }
}

// ---------------------------------------------------------------------------
// Kernel C: fused shape+pose blend + LBS (R9-exact).
// ---------------------------------------------------------------------------
__global__ __launch_bounds__(CBLK, 5) void kC(const float* __restrict__ betas,
                                              const float* __restrict__ trans,
                                              float* __restrict__ out, int Btot) {
    __shared__ __align__(16) float lr_sh[NPP][TB];
    __shared__ __align__(16) float2 G2[TBH][NJ][12];
    __shared__ __align__(16) float bet_sh[NB][TB];
    __shared__ __align__(16) float2 tr2[TBH][3];

    int b0 = blockIdx.y * TB;
    int bcnt = Btot - b0; if (bcnt > TB) bcnt = TB;
    int tid = threadIdx.x;

    for (int i = tid; i < NPP * TB; i += CBLK) {
        int p = i / TB, bb = i % TB;
        lr_sh[p][bb] = (p < NP && bb < bcnt)
                           ? g_lrot[(size_t)(b0 + bb) * NP + p] : 0.f;
    }
    for (int i = tid; i < TBH * NJ * 12; i += CBLK) {
        int q = i / (NJ * 12), k = i % (NJ * 12);
        int be = 2 * q, bo = 2 * q + 1;
        float ge = (be < bcnt) ? g_G[(size_t)(b0 + be) * NJ * 12 + k] : 0.f;
        float go = (bo < bcnt) ? g_G[(size_t)(b0 + bo) * NJ * 12 + k] : 0.f;
        G2[q][k / 12][k % 12] = make_float2(ge, go);
    }
    for (int i = tid; i < NB * TB; i += CBLK) {
        int s = i / TB, bb = i % TB;
        bet_sh[s][bb] = (bb < bcnt) ? betas[(b0 + bb) * NB + s] : 0.f;
    }
    for (int i = tid; i < TBH * 3; i += CBLK) {
        int q = i / 3, c = i % 3;
        int be = 2 * q, bo = 2 * q + 1;
        float te = (be < bcnt) ? trans[(b0 + be) * 3 + c] : 0.f;
        float to = (bo < bcnt) ? trans[(b0 + bo) * 3 + c] : 0.f;
        tr2[q][c] = make_float2(te, to);
    }
    __syncthreads();

    int v = blockIdx.x * CBLK + tid;
    int vc = v < NVERT ? v : NVERT - 1;
    bool valid = v < NVERT;

    u64 A0[TBH], A1[TBH], A2[TBH];
    {
        u64 t0 = pack2(__ldg(&g_vtT[0 * NVERT + vc]));
        u64 t1 = pack2(__ldg(&g_vtT[1 * NVERT + vc]));
        u64 t2 = pack2(__ldg(&g_vtT[2 * NVERT + vc]));
#pragma unroll
        for (int q = 0; q < TBH; ++q) { A0[q] = t0; A1[q] = t1; A2[q] = t2; }
    }

#pragma unroll
    for (int s = 0; s < NB; ++s) {
        u64 sa = pack2(__ldg(&g_sdT[(size_t)(0 * NB + s) * NVERT + vc]));
        u64 sb = pack2(__ldg(&g_sdT[(size_t)(1 * NB + s) * NVERT + vc]));
        u64 sc = pack2(__ldg(&g_sdT[(size_t)(2 * NB + s) * NVERT + vc]));
        const ulonglong2* l = reinterpret_cast<const ulonglong2*>(bet_sh[s]);
#pragma unroll
        for (int h = 0; h < TBH / 2; ++h) {
            ulonglong2 lv = l[h];
            A0[2*h]   = fma2(sa, lv.x, A0[2*h]);
            A0[2*h+1] = fma2(sa, lv.y, A0[2*h+1]);
            A1[2*h]   = fma2(sb, lv.x, A1[2*h]);
            A1[2*h+1] = fma2(sb, lv.y, A1[2*h+1]);
            A2[2*h]   = fma2(sc, lv.x, A2[2*h]);
            A2[2*h+1] = fma2(sc, lv.y, A2[2*h+1]);
        }
    }

    const uint4* pq0 = g_pdh4 + (size_t)0 * NP8 * NVERT + vc;
    const uint4* pq1 = g_pdh4 + (size_t)1 * NP8 * NVERT + vc;
    const uint4* pq2 = g_pdh4 + (size_t)2 * NP8 * NVERT + vc;

    uint4 r0a = __ldg(pq0), r0b = __ldg(pq1), r0c = __ldg(pq2);
    uint4 r1a = __ldg(pq0 + NVERT), r1b = __ldg(pq1 + NVERT), r1c = __ldg(pq2 + NVERT);

    for (int p8 = 0; p8 < NP8; ++p8) {
        uint4 r2a, r2b, r2c;
        if (p8 + 2 < NP8) {
            size_t off = (size_t)(p8 + 2) * NVERT;
            r2a = __ldg(pq0 + off);
            r2b = __ldg(pq1 + off);
            r2c = __ldg(pq2 + off);
        } else {
            r2a = r2b = r2c = make_uint4(0, 0, 0, 0);
        }
#pragma unroll
        for (int w = 0; w < 4; ++w) {
            unsigned ua = (w == 0) ? r0a.x : (w == 1) ? r0a.y : (w == 2) ? r0a.z : r0a.w;
            unsigned ub = (w == 0) ? r0b.x : (w == 1) ? r0b.y : (w == 2) ? r0b.z : r0b.w;
            unsigned uc = (w == 0) ? r0c.x : (w == 1) ? r0c.y : (w == 2) ? r0c.z : r0c.w;
#pragma unroll
            for (int e = 0; e < 2; ++e) {
                u64 pa = e ? splat_hi(ua) : splat_lo(ua);
                u64 pb = e ? splat_hi(ub) : splat_lo(ub);
                u64 pc = e ? splat_hi(uc) : splat_lo(uc);
                const ulonglong2* l =
                    reinterpret_cast<const ulonglong2*>(lr_sh[p8 * 8 + w * 2 + e]);
#pragma unroll
                for (int h = 0; h < TBH / 2; ++h) {
                    ulonglong2 lv = l[h];
                    A0[2*h]   = fma2(pa, lv.x, A0[2*h]);
                    A0[2*h+1] = fma2(pa, lv.y, A0[2*h+1]);
                    A1[2*h]   = fma2(pb, lv.x, A1[2*h]);
                    A1[2*h+1] = fma2(pb, lv.y, A1[2*h+1]);
                    A2[2*h]   = fma2(pc, lv.x, A2[2*h]);
                    A2[2*h+1] = fma2(pc, lv.y, A2[2*h+1]);
                }
            }
        }
        r0a = r1a; r0b = r1b; r0c = r1c;
        r1a = r2a; r1b = r2b; r1c = r2c;
    }

    float wv[NJ];
#pragma unroll
    for (int j = 0; j < NJ; ++j) wv[j] = __ldg(&g_wT[(size_t)j * NVERT + vc]);

#pragma unroll
    for (int q = 0; q < TBH; ++q) {
        u64 T[12];
#pragma unroll
        for (int k = 0; k < 12; ++k) T[k] = 0ull;
        const ulonglong2* gq = reinterpret_cast<const ulonglong2*>(G2[q][0]);
#pragma unroll 4
        for (int j = 0; j < NJ; ++j) {
            u64 wj = pack2(wv[j]);
            const ulonglong2* g = gq + j * 6;
#pragma unroll
            for (int k = 0; k < 6; ++k) {
                ulonglong2 gg = g[k];
                T[2*k]   = fma2(wj, gg.x, T[2*k]);
                T[2*k+1] = fma2(wj, gg.y, T[2*k+1]);
            }
        }
        u64 ox = fma2(T[0], A0[q], fma2(T[1], A1[q], fma2(T[2], A2[q], T[3])));
        u64 oy = fma2(T[4], A0[q], fma2(T[5], A1[q], fma2(T[6], A2[q], T[7])));
        u64 oz = fma2(T[8], A0[q], fma2(T[9], A1[q], fma2(T[10], A2[q], T[11])));
        const u64* tq = reinterpret_cast<const u64*>(tr2[q]);
        ox = add2(ox, tq[0]);
        oy = add2(oy, tq[1]);
        oz = add2(oz, tq[2]);
        float xe, xo, ye, yo, ze, zo;
        unpack2(ox, xe, xo);
        unpack2(oy, ye, yo);
        unpack2(oz, ze, zo);
        int be = 2 * q, bo = 2 * q + 1;
        if (valid && be < bcnt) {
            size_t o = ((size_t)(b0 + be) * NVERT + v) * 3;
            out[o + 0] = xe; out[o + 1] = ye; out[o + 2] = ze;
        }
        if (valid && bo < bcnt) {
            size_t o = ((size_t)(b0 + bo) * NVERT + v) * 3;
            out[o + 0] = xo; out[o + 1] = yo; out[o + 2] = zo;
        }
    }
}

// ---------------------------------------------------------------------------
// Kernel D: joints = J_regressor @ result, grid (B, VSPL), atomic finish.
// ---------------------------------------------------------------------------
__global__ __launch_bounds__(256) void kD(const float* __restrict__ Jr,
                                          const float* __restrict__ result,
                                          float* __restrict__ joints) {
    int b = blockIdx.x;
    int sp = blockIdx.y;
    int v0 = sp * VCH;
    int v1 = v0 + VCH; if (v1 > NVERT) v1 = NVERT;

    float acc[NJ][3];
#pragma unroll
    for (int j = 0; j < NJ; ++j) { acc[j][0] = 0.f; acc[j][1] = 0.f; acc[j][2] = 0.f; }

    const float* rb = result + (size_t)b * NVERT * 3;
    for (int v = v0 + threadIdx.x; v < v1; v += 256) {
        float rx = rb[v * 3 + 0], ry = rb[v * 3 + 1], rz = rb[v * 3 + 2];
#pragma unroll
        for (int j = 0; j < NJ; ++j) {
            float w = __ldg(&Jr[j * NVERT + v]);
            acc[j][0] = fmaf(w, rx, acc[j][0]);
            acc[j][1] = fmaf(w, ry, acc[j][1]);
            acc[j][2] = fmaf(w, rz, acc[j][2]);
        }
    }
    __shared__ float sm[NJ * 3];
    if (threadIdx.x < NJ * 3) sm[threadIdx.x] = 0.f;
    __syncthreads();
#pragma unroll
    for (int j = 0; j < NJ; ++j) {
#pragma unroll
        for (int c = 0; c < 3; ++c) {
            float x = acc[j][c];
#pragma unroll
            for (int off = 16; off > 0; off >>= 1)
                x += __shfl_xor_sync(0xffffffffu, x, off);
            if ((threadIdx.x & 31) == 0) atomicAdd(&sm[j * 3 + c], x);
        }
    }
    __syncthreads();
    if (threadIdx.x < NJ * 3)
        atomicAdd(&joints[(size_t)b * NJ * 3 + threadIdx.x], sm[threadIdx.x]);
}

// ---------------------------------------------------------------------------
extern "C" void kernel_launch(void* const* d_in, const int* in_sizes, int n_in,
                              void* d_out, int out_size) {
    const float* betas  = (const float*)d_in[0];
    const float* thetas = (const float*)d_in[1];
    const float* trans  = (const float*)d_in[2];
    const float* scale  = (const float*)d_in[3];
    const float* vt     = (const float*)d_in[4];
    const float* sd     = (const float*)d_in[5];
    const float* pd     = (const float*)d_in[6];
    const float* Jr     = (const float*)d_in[7];
    const float* wgt    = (const float*)d_in[8];

    int Btot = in_sizes[0] / NB;
    float* out = (float*)d_out;
    float* joints = out + (size_t)Btot * NVERT * 3;

    dim3 tb(32, 8);
    dim3 gT((NVERT + 31) / 32, (NPP + 31) / 32, 6);
    kT<<<gT, tb>>>(pd, wgt, sd, vt);

    kA<<<NJ, 256>>>(Jr, vt, sd);
    kB<<<(Btot + BWB - 1) / BWB, 32 * BWB>>>(betas, thetas, scale, joints, Btot);

    dim3 gc((NVERT + CBLK - 1) / CBLK, (Btot + TB - 1) / TB);
    kC<<<gc, CBLK>>>(betas, trans, out, Btot);

    dim3 gd(Btot, VSPL);
    kD<<<gd, 256>>>(Jr, out, joints);
}

// round 17
// speedup vs baseline: 1.5585x; 1.4734x over previous
#include <cuda_runtime.h>
#include <cuda_bf16.h>

#define NVERT 6890
#define NJ 24
#define NB 10
#define NP 207
#define NP8 26
#define NPP (NP8*8)
#define MAXB 1024
#define TB 8
#define TBH 4
#define CBLK 128
#define VSPL 8
#define VCH 862
#define BWB 8            // batches per kB block
#define DWB 8            // batches (warps) per kD block

typedef unsigned long long u64;

__device__ __forceinline__ u64 pack2(float x) {
    u64 r; asm("mov.b64 %0,{%1,%1};" : "=l"(r) : "f"(x)); return r;
}
__device__ __forceinline__ void unpack2(u64 v, float& a, float& b) {
    asm("mov.b64 {%0,%1},%2;" : "=f"(a), "=f"(b) : "l"(v));
}
__device__ __forceinline__ u64 fma2(u64 a, u64 b, u64 c) {
    u64 d; asm("fma.rn.f32x2 %0,%1,%2,%3;" : "=l"(d) : "l"(a), "l"(b), "l"(c)); return d;
}
__device__ __forceinline__ u64 add2(u64 a, u64 b) {
    u64 d; asm("add.rn.f32x2 %0,%1,%2;" : "=l"(d) : "l"(a), "l"(b)); return d;
}
__device__ __forceinline__ u64 splat_lo(unsigned u) {
    unsigned f = u << 16;
    u64 r; asm("mov.b64 %0,{%1,%1};" : "=l"(r) : "r"(f)); return r;
}
__device__ __forceinline__ u64 splat_hi(unsigned u) {
    unsigned f = u & 0xffff0000u;
    u64 r; asm("mov.b64 %0,{%1,%1};" : "=l"(r) : "r"(f)); return r;
}

__constant__ int c_par[NJ] = {-1, 0, 0, 0, 1, 2, 3, 4, 5, 6, 7, 8, 9, 9, 9,
                              12, 13, 14, 16, 17, 18, 19, 20, 21};

__device__ float g_JrT[NJ * 3];
__device__ float g_JrS[NJ * 3 * NB];
__device__ float g_G[MAXB * NJ * 12];
__device__ float g_lrot[MAXB * NP];

__device__ uint4 g_pdh4[(size_t)3 * NP8 * NVERT];
__device__ float g_sdT[3 * NB * NVERT];
__device__ float g_wT[NJ * NVERT];
__device__ float g_vtT[3 * NVERT];

// ---------------------------------------------------------------------------
// kT: ALL transposes in one launch.
// z<3: pd coord c=z -> g_pdh4 bf16-packed. z=3..5 (y==0 only): wgt/sd/vt.
// ---------------------------------------------------------------------------
__global__ __launch_bounds__(256) void kT(const float* __restrict__ pd,
                                          const float* __restrict__ wgt,
                                          const float* __restrict__ sd,
                                          const float* __restrict__ vt) {
    __shared__ float tile[32][33];
    int z = blockIdx.z;
    if (z < 3) {
        int c = z;
        int p0 = blockIdx.y * 32, v0 = blockIdx.x * 32;
        for (int r = threadIdx.y; r < 32; r += 8) {
            int v = v0 + r, p = p0 + threadIdx.x;
            tile[r][threadIdx.x] =
                (v < NVERT && p < NP) ? pd[((size_t)v * 3 + c) * NP + p] : 0.f;
        }
        __syncthreads();
        int p8l = threadIdx.y;
        int vl = threadIdx.x;
        if (p8l < 4) {
            int p8g = blockIdx.y * 4 + p8l;
            int v = v0 + vl;
            if (p8g < NP8 && v < NVERT) {
                unsigned w[4];
#pragma unroll
                for (int k = 0; k < 4; ++k) {
                    float f0 = tile[vl][p8l * 8 + 2 * k + 0];
                    float f1 = tile[vl][p8l * 8 + 2 * k + 1];
                    unsigned lo = __bfloat16_as_ushort(__float2bfloat16(f0));
                    unsigned hi = __bfloat16_as_ushort(__float2bfloat16(f1));
                    w[k] = lo | (hi << 16);
                }
                g_pdh4[((size_t)c * NP8 + p8g) * NVERT + v] =
                    make_uint4(w[0], w[1], w[2], w[3]);
            }
        }
    } else {
        if (blockIdx.y != 0) return;
        const float* in; float* out; int K;
        if (z == 3)      { in = wgt; out = g_wT;  K = NJ; }
        else if (z == 4) { in = sd;  out = g_sdT; K = 3 * NB; }
        else             { in = vt;  out = g_vtT; K = 3; }
        int v0 = blockIdx.x * 32;
        for (int r = threadIdx.y; r < 32; r += 8) {
            int v = v0 + r, k = threadIdx.x;
            tile[r][k] = (v < NVERT && k < K) ? in[(size_t)v * K + k] : 0.f;
        }
        __syncthreads();
        for (int r = threadIdx.y; r < 32; r += 8) {
            int k = r, v = v0 + threadIdx.x;
            if (k < K && v < NVERT) out[(size_t)k * NVERT + v] = tile[threadIdx.x][r];
        }
    }
}

// ---------------------------------------------------------------------------
// Kernel A: fold J_regressor into v_template and shapedirs (coalesced reads
// from transposed layouts — kT precedes this).
// ---------------------------------------------------------------------------
__global__ __launch_bounds__(256) void kA(const float* __restrict__ Jr) {
    int j = blockIdx.x;
    float acc[33];
#pragma unroll
    for (int k = 0; k < 33; ++k) acc[k] = 0.f;

    for (int v = threadIdx.x; v < NVERT; v += blockDim.x) {
        float w = Jr[j * NVERT + v];
#pragma unroll
        for (int c = 0; c < 3; ++c)
            acc[c] = fmaf(w, __ldg(&g_vtT[c * NVERT + v]), acc[c]);
#pragma unroll
        for (int k = 0; k < 3 * NB; ++k)
            acc[3 + k] = fmaf(w, __ldg(&g_sdT[(size_t)k * NVERT + v]), acc[3 + k]);
    }
#pragma unroll
    for (int k = 0; k < 33; ++k) {
#pragma unroll
        for (int off = 16; off > 0; off >>= 1)
            acc[k] += __shfl_xor_sync(0xffffffffu, acc[k], off);
    }
    __shared__ float sm[33];
    if (threadIdx.x < 33) sm[threadIdx.x] = 0.f;
    __syncthreads();
    if ((threadIdx.x & 31) == 0) {
#pragma unroll
        for (int k = 0; k < 33; ++k) atomicAdd(&sm[k], acc[k]);
    }
    __syncthreads();
    if (threadIdx.x < 3) g_JrT[j * 3 + threadIdx.x] = sm[threadIdx.x];
    if (threadIdx.x >= 3 && threadIdx.x < 33)
        g_JrS[j * 3 * NB + threadIdx.x - 3] = sm[threadIdx.x];
}

// ---------------------------------------------------------------------------
// Kernel B: 8 batches per block, one warp each. Warp-private smem slices.
// ---------------------------------------------------------------------------
__global__ __launch_bounds__(32 * BWB) void kB(const float* __restrict__ betas,
                                               const float* __restrict__ thetas,
                                               const float* __restrict__ scale,
                                               float* __restrict__ joints,
                                               int Btot) {
    int w = threadIdx.x >> 5;
    int t = threadIdx.x & 31;
    int b = blockIdx.x * BWB + w;
    if (b >= Btot) return;

    __shared__ float R[BWB][NJ][9];
    __shared__ float J[BWB][NJ][3];
    __shared__ float W[BWB][NJ][12];

    for (int idx = t; idx < NJ * 3; idx += 32)
        joints[(size_t)b * NJ * 3 + idx] = 0.f;

    if (t < NJ) {
#pragma unroll
        for (int c = 0; c < 3; ++c) {
            float s = g_JrT[t * 3 + c];
#pragma unroll
            for (int k = 0; k < NB; ++k)
                s = fmaf(g_JrS[t * 3 * NB + c * NB + k], betas[b * NB + k], s);
            J[w][t][c] = s;
        }
        float x = thetas[b * NJ * 3 + t * 3 + 0];
        float y = thetas[b * NJ * 3 + t * 3 + 1];
        float z = thetas[b * NJ * 3 + t * 3 + 2];
        float th = sqrtf(x * x + y * y + z * z) + 1e-8f;
        float rx = x / th, ry = y / th, rz = z / th;
        float cth = cosf(th), sth = sinf(th), ic = 1.f - cth;
        float r[9];
        r[0] = cth + ic * rx * rx;
        r[1] = ic * rx * ry - sth * rz;
        r[2] = ic * rx * rz + sth * ry;
        r[3] = ic * rx * ry + sth * rz;
        r[4] = cth + ic * ry * ry;
        r[5] = ic * ry * rz - sth * rx;
        r[6] = ic * rx * rz - sth * ry;
        r[7] = ic * ry * rz + sth * rx;
        r[8] = cth + ic * rz * rz;
        if (t == 0) {
            float sc = scale[0];
#pragma unroll
            for (int k = 0; k < 9; ++k) r[k] *= sc;
        }
#pragma unroll
        for (int k = 0; k < 9; ++k) R[w][t][k] = r[k];
    }
    __syncwarp();

    if (t == 0) {
#pragma unroll
        for (int rr = 0; rr < 3; ++rr) {
            W[w][0][rr * 4 + 0] = R[w][0][rr * 3 + 0];
            W[w][0][rr * 4 + 1] = R[w][0][rr * 3 + 1];
            W[w][0][rr * 4 + 2] = R[w][0][rr * 3 + 2];
            W[w][0][rr * 4 + 3] = J[w][0][rr];
        }
        for (int i = 1; i < NJ; ++i) {
            int p = c_par[i];
            float tx = J[w][i][0] - J[w][p][0];
            float ty = J[w][i][1] - J[w][p][1];
            float tz = J[w][i][2] - J[w][p][2];
#pragma unroll
            for (int rr = 0; rr < 3; ++rr) {
                float w0 = W[w][p][rr * 4 + 0], w1 = W[w][p][rr * 4 + 1],
                      w2 = W[w][p][rr * 4 + 2], w3 = W[w][p][rr * 4 + 3];
#pragma unroll
                for (int cc = 0; cc < 3; ++cc)
                    W[w][i][rr * 4 + cc] = w0 * R[w][i][0 * 3 + cc] +
                                           w1 * R[w][i][1 * 3 + cc] +
                                           w2 * R[w][i][2 * 3 + cc];
                W[w][i][rr * 4 + 3] = w0 * tx + w1 * ty + w2 * tz + w3;
            }
        }
    }
    __syncwarp();

    if (t < NJ) {
        float* g = g_G + ((size_t)b * NJ + t) * 12;
#pragma unroll
        for (int rr = 0; rr < 3; ++rr) {
            float w0 = W[w][t][rr * 4 + 0], w1 = W[w][t][rr * 4 + 1],
                  w2 = W[w][t][rr * 4 + 2], w3 = W[w][t][rr * 4 + 3];
            g[rr * 4 + 0] = w0;
            g[rr * 4 + 1] = w1;
            g[rr * 4 + 2] = w2;
            g[rr * 4 + 3] = w3 - (w0 * J[w][t][0] + w1 * J[w][t][1] + w2 * J[w][t][2]);
        }
    }
    for (int idx = t; idx < NP; idx += 32) {
        int j = idx / 9 + 1;
        int rc = idx % 9;
        float v = R[w][j][rc];
        if (rc == 0 || rc == 4 || rc == 8) v -= 1.f;
        g_lrot[(size_t)b * NP + idx] = v;
    }
}

// ---------------------------------------------------------------------------
// Kernel C: fused shape+pose blend + LBS (R16-measured version, unchanged).
// ---------------------------------------------------------------------------
__global__ __launch_bounds__(CBLK, 5) void kC(const float* __restrict__ betas,
                                              const float* __restrict__ trans,
                                              float* __restrict__ out, int Btot) {
    __shared__ __align__(16) float lr_sh[NPP][TB];
    __shared__ __align__(16) float2 G2[TBH][NJ][12];
    __shared__ __align__(16) float bet_sh[NB][TB];
    __shared__ __align__(16) float2 tr2[TBH][3];

    int b0 = blockIdx.y * TB;
    int bcnt = Btot - b0; if (bcnt > TB) bcnt = TB;
    int tid = threadIdx.x;

    for (int i = tid; i < NPP * TB; i += CBLK) {
        int p = i / TB, bb = i % TB;
        lr_sh[p][bb] = (p < NP && bb < bcnt)
                           ? g_lrot[(size_t)(b0 + bb) * NP + p] : 0.f;
    }
    for (int i = tid; i < TBH * NJ * 12; i += CBLK) {
        int q = i / (NJ * 12), k = i % (NJ * 12);
        int be = 2 * q, bo = 2 * q + 1;
        float ge = (be < bcnt) ? g_G[(size_t)(b0 + be) * NJ * 12 + k] : 0.f;
        float go = (bo < bcnt) ? g_G[(size_t)(b0 + bo) * NJ * 12 + k] : 0.f;
        G2[q][k / 12][k % 12] = make_float2(ge, go);
    }
    for (int i = tid; i < NB * TB; i += CBLK) {
        int s = i / TB, bb = i % TB;
        bet_sh[s][bb] = (bb < bcnt) ? betas[(b0 + bb) * NB + s] : 0.f;
    }
    for (int i = tid; i < TBH * 3; i += CBLK) {
        int q = i / 3, c = i % 3;
        int be = 2 * q, bo = 2 * q + 1;
        float te = (be < bcnt) ? trans[(b0 + be) * 3 + c] : 0.f;
        float to = (bo < bcnt) ? trans[(b0 + bo) * 3 + c] : 0.f;
        tr2[q][c] = make_float2(te, to);
    }
    __syncthreads();

    int v = blockIdx.x * CBLK + tid;
    int vc = v < NVERT ? v : NVERT - 1;
    bool valid = v < NVERT;

    u64 A0[TBH], A1[TBH], A2[TBH];
    {
        u64 t0 = pack2(__ldg(&g_vtT[0 * NVERT + vc]));
        u64 t1 = pack2(__ldg(&g_vtT[1 * NVERT + vc]));
        u64 t2 = pack2(__ldg(&g_vtT[2 * NVERT + vc]));
#pragma unroll
        for (int q = 0; q < TBH; ++q) { A0[q] = t0; A1[q] = t1; A2[q] = t2; }
    }

#pragma unroll
    for (int s = 0; s < NB; ++s) {
        u64 sa = pack2(__ldg(&g_sdT[(size_t)(0 * NB + s) * NVERT + vc]));
        u64 sb = pack2(__ldg(&g_sdT[(size_t)(1 * NB + s) * NVERT + vc]));
        u64 sc = pack2(__ldg(&g_sdT[(size_t)(2 * NB + s) * NVERT + vc]));
        const ulonglong2* l = reinterpret_cast<const ulonglong2*>(bet_sh[s]);
#pragma unroll
        for (int h = 0; h < TBH / 2; ++h) {
            ulonglong2 lv = l[h];
            A0[2*h]   = fma2(sa, lv.x, A0[2*h]);
            A0[2*h+1] = fma2(sa, lv.y, A0[2*h+1]);
            A1[2*h]   = fma2(sb, lv.x, A1[2*h]);
            A1[2*h+1] = fma2(sb, lv.y, A1[2*h+1]);
            A2[2*h]   = fma2(sc, lv.x, A2[2*h]);
            A2[2*h+1] = fma2(sc, lv.y, A2[2*h+1]);
        }
    }

    const uint4* pq0 = g_pdh4 + (size_t)0 * NP8 * NVERT + vc;
    const uint4* pq1 = g_pdh4 + (size_t)1 * NP8 * NVERT + vc;
    const uint4* pq2 = g_pdh4 + (size_t)2 * NP8 * NVERT + vc;

    uint4 r0a = __ldg(pq0), r0b = __ldg(pq1), r0c = __ldg(pq2);
    uint4 r1a = __ldg(pq0 + NVERT), r1b = __ldg(pq1 + NVERT), r1c = __ldg(pq2 + NVERT);

    for (int p8 = 0; p8 < NP8; ++p8) {
        uint4 r2a, r2b, r2c;
        if (p8 + 2 < NP8) {
            size_t off = (size_t)(p8 + 2) * NVERT;
            r2a = __ldg(pq0 + off);
            r2b = __ldg(pq1 + off);
            r2c = __ldg(pq2 + off);
        } else {
            r2a = r2b = r2c = make_uint4(0, 0, 0, 0);
        }
#pragma unroll
        for (int w = 0; w < 4; ++w) {
            unsigned ua = (w == 0) ? r0a.x : (w == 1) ? r0a.y : (w == 2) ? r0a.z : r0a.w;
            unsigned ub = (w == 0) ? r0b.x : (w == 1) ? r0b.y : (w == 2) ? r0b.z : r0b.w;
            unsigned uc = (w == 0) ? r0c.x : (w == 1) ? r0c.y : (w == 2) ? r0c.z : r0c.w;
#pragma unroll
            for (int e = 0; e < 2; ++e) {
                u64 pa = e ? splat_hi(ua) : splat_lo(ua);
                u64 pb = e ? splat_hi(ub) : splat_lo(ub);
                u64 pc = e ? splat_hi(uc) : splat_lo(uc);
                const ulonglong2* l =
                    reinterpret_cast<const ulonglong2*>(lr_sh[p8 * 8 + w * 2 + e]);
#pragma unroll
                for (int h = 0; h < TBH / 2; ++h) {
                    ulonglong2 lv = l[h];
                    A0[2*h]   = fma2(pa, lv.x, A0[2*h]);
                    A0[2*h+1] = fma2(pa, lv.y, A0[2*h+1]);
                    A1[2*h]   = fma2(pb, lv.x, A1[2*h]);
                    A1[2*h+1] = fma2(pb, lv.y, A1[2*h+1]);
                    A2[2*h]   = fma2(pc, lv.x, A2[2*h]);
                    A2[2*h+1] = fma2(pc, lv.y, A2[2*h+1]);
                }
            }
        }
        r0a = r1a; r0b = r1b; r0c = r1c;
        r1a = r2a; r1b = r2b; r1c = r2c;
    }

    float wv[NJ];
#pragma unroll
    for (int j = 0; j < NJ; ++j) wv[j] = __ldg(&g_wT[(size_t)j * NVERT + vc]);

#pragma unroll
    for (int q = 0; q < TBH; ++q) {
        u64 T[12];
#pragma unroll
        for (int k = 0; k < 12; ++k) T[k] = 0ull;
        const ulonglong2* gq = reinterpret_cast<const ulonglong2*>(G2[q][0]);
#pragma unroll 4
        for (int j = 0; j < NJ; ++j) {
            u64 wj = pack2(wv[j]);
            const ulonglong2* g = gq + j * 6;
#pragma unroll
            for (int k = 0; k < 6; ++k) {
                ulonglong2 gg = g[k];
                T[2*k]   = fma2(wj, gg.x, T[2*k]);
                T[2*k+1] = fma2(wj, gg.y, T[2*k+1]);
            }
        }
        u64 ox = fma2(T[0], A0[q], fma2(T[1], A1[q], fma2(T[2], A2[q], T[3])));
        u64 oy = fma2(T[4], A0[q], fma2(T[5], A1[q], fma2(T[6], A2[q], T[7])));
        u64 oz = fma2(T[8], A0[q], fma2(T[9], A1[q], fma2(T[10], A2[q], T[11])));
        const u64* tq = reinterpret_cast<const u64*>(tr2[q]);
        ox = add2(ox, tq[0]);
        oy = add2(oy, tq[1]);
        oz = add2(oz, tq[2]);
        float xe, xo, ye, yo, ze, zo;
        unpack2(ox, xe, xo);
        unpack2(oy, ye, yo);
        unpack2(oz, ze, zo);
        int be = 2 * q, bo = 2 * q + 1;
        if (valid && be < bcnt) {
            size_t o = ((size_t)(b0 + be) * NVERT + v) * 3;
            out[o + 0] = xe; out[o + 1] = ye; out[o + 2] = ze;
        }
        if (valid && bo < bcnt) {
            size_t o = ((size_t)(b0 + bo) * NVERT + v) * 3;
            out[o + 0] = xo; out[o + 1] = yo; out[o + 2] = zo;
        }
    }
}

// ---------------------------------------------------------------------------
// Kernel D3: joints += Jr @ result. Block = 8 warps = 8 PARALLEL batches, one
// vsplit slice. Jr slice (24 x vcnt, fp32) staged once in dynamic smem and
// reused by all 8 warps. No block barriers in the hot path.
// ---------------------------------------------------------------------------
extern __shared__ float JrS[];

__global__ __launch_bounds__(32 * DWB) void kD3(const float* __restrict__ Jr,
                                                const float* __restrict__ result,
                                                float* __restrict__ joints,
                                                int Btot) {
    int sp = blockIdx.y;
    int v0 = sp * VCH;
    int vcnt = NVERT - v0; if (vcnt > VCH) vcnt = VCH;
    int tid = threadIdx.x;

    for (int i = tid; i < NJ * vcnt; i += 32 * DWB) {
        int j = i / vcnt, vv = i - j * vcnt;
        JrS[i] = Jr[(size_t)j * NVERT + v0 + vv];
    }
    __syncthreads();

    int w = tid >> 5, lane = tid & 31;
    int b = blockIdx.x * DWB + w;
    if (b >= Btot) return;

    float acc[NJ][3];
#pragma unroll
    for (int j = 0; j < NJ; ++j) { acc[j][0] = 0.f; acc[j][1] = 0.f; acc[j][2] = 0.f; }

    const float* rb = result + ((size_t)b * NVERT + v0) * 3;
    for (int i = lane; i < vcnt; i += 32) {
        float rx = rb[i * 3 + 0], ry = rb[i * 3 + 1], rz = rb[i * 3 + 2];
#pragma unroll
        for (int j = 0; j < NJ; ++j) {
            float wj = JrS[j * vcnt + i];
            acc[j][0] = fmaf(wj, rx, acc[j][0]);
            acc[j][1] = fmaf(wj, ry, acc[j][1]);
            acc[j][2] = fmaf(wj, rz, acc[j][2]);
        }
    }
#pragma unroll
    for (int j = 0; j < NJ; ++j) {
#pragma unroll
        for (int c = 0; c < 3; ++c) {
            float x = acc[j][c];
#pragma unroll
            for (int off = 16; off > 0; off >>= 1)
                x += __shfl_xor_sync(0xffffffffu, x, off);
            if (lane == 0)
                atomicAdd(&joints[(size_t)b * NJ * 3 + j * 3 + c], x);
        }
    }
}

// ---------------------------------------------------------------------------
extern "C" void kernel_launch(void* const* d_in, const int* in_sizes, int n_in,
                              void* d_out, int out_size) {
    const float* betas  = (const float*)d_in[0];
    const float* thetas = (const float*)d_in[1];
    const float* trans  = (const float*)d_in[2];
    const float* scale  = (const float*)d_in[3];
    const float* vt     = (const float*)d_in[4];
    const float* sd     = (const float*)d_in[5];
    const float* pd     = (const float*)d_in[6];
    const float* Jr     = (const float*)d_in[7];
    const float* wgt    = (const float*)d_in[8];

    int Btot = in_sizes[0] / NB;
    float* out = (float*)d_out;
    float* joints = out + (size_t)Btot * NVERT * 3;

    dim3 tb(32, 8);
    dim3 gT((NVERT + 31) / 32, (NPP + 31) / 32, 6);
    kT<<<gT, tb>>>(pd, wgt, sd, vt);

    kA<<<NJ, 256>>>(Jr);
    kB<<<(Btot + BWB - 1) / BWB, 32 * BWB>>>(betas, thetas, scale, joints, Btot);

    dim3 gc((NVERT + CBLK - 1) / CBLK, (Btot + TB - 1) / TB);
    kC<<<gc, CBLK>>>(betas, trans, out, Btot);

    int jrBytes = NJ * VCH * 4;   // 82,752 B
    static int attr_set = 0;
    if (!attr_set) {
        cudaFuncSetAttribute(kD3, cudaFuncAttributeMaxDynamicSharedMemorySize,
                             jrBytes);
        attr_set = 1;
    }
    dim3 gd((Btot + DWB - 1) / DWB, VSPL);
    kD3<<<gd, 32 * DWB, jrBytes>>>(Jr, out, joints, Btot);
}